// round 1
// baseline (speedup 1.0000x reference)
#include <cuda_runtime.h>
#include <math.h>

#define BB   4
#define NN   16384
#define CIN0 64
#define COUT 128
#define RR   32
#define NVOX (BB*RR*RR*RR)   /* 131072 */

// ---------------- scratch (device globals; no allocation in kernel_launch) ----
__device__ float g_grid[(size_t)NVOX * CIN0];        // [b][x][y][z][64]   33.5 MB
__device__ float g_cnt [NVOX];                       //                     0.5 MB
__device__ float g_h1  [(size_t)NVOX * COUT];        // [b][x][y][z][128]  67 MB
__device__ float g_h2  [(size_t)NVOX * COUT];        //                    67 MB
__device__ float g_pf  [(size_t)BB * NN * COUT];     // [b][n][c]          33.5 MB
__device__ float g_stats[BB * 8 * 2];                // per (b,group): sum,sumsq -> mu,rs
__device__ float g_wt1 [CIN0 * 27 * COUT];           // [ci][tap][co]
__device__ float g_wt2 [COUT * 27 * COUT];

// ---------------- zero scratch ------------------------------------------------
__global__ void zero_scratch_kernel() {
    const long NG = (long)NVOX * CIN0;
    const long NC = NVOX;
    const long NS = BB * 8 * 2;
    const long total = NG + NC + NS;
    for (long i = (long)blockIdx.x * blockDim.x + threadIdx.x; i < total;
         i += (long)gridDim.x * blockDim.x) {
        if (i < NG)            g_grid[i] = 0.f;
        else if (i < NG + NC)  g_cnt[i - NG] = 0.f;
        else                   g_stats[i - NG - NC] = 0.f;
    }
}

// ---------------- weight transpose: w[co][ci][tap] -> wt[ci][tap][co] ---------
template <int CIN>
__global__ void wt_transpose_kernel(const float* __restrict__ w) {
    float* dst = (CIN == CIN0) ? g_wt1 : g_wt2;
    int total = CIN * 27 * COUT;
    for (int i = blockIdx.x * blockDim.x + threadIdx.x; i < total;
         i += gridDim.x * blockDim.x) {
        int co  = i / (CIN * 27);
        int r   = i - co * (CIN * 27);
        int ci  = r / 27;
        int tap = r - ci * 27;
        dst[(ci * 27 + tap) * COUT + co] = w[i];
    }
}

// ---------------- voxelize: scatter-add ---------------------------------------
__global__ void scatter_kernel(const float* __restrict__ coords,
                               const float* __restrict__ feats) {
    int idx = blockIdx.x * blockDim.x + threadIdx.x;     // over 65536*64
    if (idx >= BB * NN * CIN0) return;
    int ci = idx & (CIN0 - 1);
    int gp = idx >> 6;                                   // global point
    int b  = gp >> 14;
    int n  = gp & (NN - 1);
    float cx = coords[gp * 3 + 0] * (float)RR;
    float cy = coords[gp * 3 + 1] * (float)RR;
    float cz = coords[gp * 3 + 2] * (float)RR;
    int ix = min(max((int)floorf(cx), 0), RR - 1);
    int iy = min(max((int)floorf(cy), 0), RR - 1);
    int iz = min(max((int)floorf(cz), 0), RR - 1);
    int vox = ((b * RR + ix) * RR + iy) * RR + iz;
    atomicAdd(&g_grid[(size_t)vox * CIN0 + ci],
              feats[((size_t)b * CIN0 + ci) * NN + n]);
    if (ci == 0) atomicAdd(&g_cnt[vox], 1.0f);
}

__global__ void vox_norm_kernel() {
    long total = (long)NVOX * CIN0;
    for (long i = (long)blockIdx.x * blockDim.x + threadIdx.x; i < total;
         i += (long)gridDim.x * blockDim.x) {
        long v = i >> 6;
        float c = g_cnt[v];
        g_grid[i] *= 1.0f / fmaxf(c, 1.0f);
    }
}

// ---------------- fused conv3x3x3 + bias + per-voxel GN(16) + SiLU ------------
// block = (x, y, b) pencil over z. 128 threads: lane c0 = tid&31 (cout base),
// zq = tid>>5 (z quarter). Each thread: 4 couts (c0 + 32j) x 8 z.
template <int CIN>
__global__ void __launch_bounds__(128)
conv_gn_silu_kernel(const float* __restrict__ bias,
                    const float* __restrict__ gamma,
                    const float* __restrict__ beta) {
    const float* in = (CIN == CIN0) ? g_grid : g_h1;
    const float* wt = (CIN == CIN0) ? g_wt1 : g_wt2;
    float* outp     = (CIN == CIN0) ? g_h1  : g_h2;

    constexpr int CHUNK = 16;
    __shared__ float s_in[9 * 34 * CHUNK];               // [q][zp][ci]  19.6 KB

    const int tid = threadIdx.x;
    const int c0  = tid & 31;
    const int zq  = tid >> 5;
    const int z0  = zq * 8;
    const int bx = blockIdx.x, by = blockIdx.y, bb = blockIdx.z;

    float acc[4][8];
#pragma unroll
    for (int j = 0; j < 4; j++)
#pragma unroll
        for (int z = 0; z < 8; z++) acc[j][z] = 0.f;

    for (int cb = 0; cb < CIN; cb += CHUNK) {
        __syncthreads();
        // load halo: 9 columns x 34 zp x 16 ci, as float4
        for (int i = tid; i < 9 * 34 * (CHUNK / 4); i += 128) {
            int ci4 = i % (CHUNK / 4);
            int zp  = (i / (CHUNK / 4)) % 34;
            int q   = i / ((CHUNK / 4) * 34);
            int dx = q / 3, dy = q % 3;
            int gx = bx + dx - 1, gy = by + dy - 1, gz = zp - 1;
            float4 v = make_float4(0.f, 0.f, 0.f, 0.f);
            if ((unsigned)gx < RR && (unsigned)gy < RR && (unsigned)gz < RR) {
                v = *(const float4*)&in[((((size_t)bb * RR + gx) * RR + gy) * RR + gz) * CIN
                                        + cb + ci4 * 4];
            }
            *(float4*)&s_in[(q * 34 + zp) * CHUNK + ci4 * 4] = v;
        }
        __syncthreads();

        for (int ci = 0; ci < CHUNK; ci++) {
#pragma unroll
            for (int q = 0; q < 9; q++) {
#pragma unroll
                for (int dz = 0; dz < 3; dz++) {
                    int tap = q * 3 + dz;
                    const float* wp = &wt[((size_t)(cb + ci) * 27 + tap) * COUT + c0];
                    float w0 = wp[0], w1 = wp[32], w2 = wp[64], w3 = wp[96];
                    const float* sp = &s_in[(q * 34 + z0 + dz) * CHUNK + ci];
#pragma unroll
                    for (int z = 0; z < 8; z++) {
                        float x = sp[z * CHUNK];
                        acc[0][z] += w0 * x;
                        acc[1][z] += w1 * x;
                        acc[2][z] += w2 * x;
                        acc[3][z] += w3 * x;
                    }
                }
            }
        }
    }

    // epilogue: bias + GroupNorm over 16 channels (16-lane segments) + SiLU
    float bv[4], gm[4], bt[4];
#pragma unroll
    for (int j = 0; j < 4; j++) {
        int c = c0 + 32 * j;
        bv[j] = bias[c]; gm[j] = gamma[c]; bt[j] = beta[c];
    }
    size_t vbase = (((size_t)bb * RR + bx) * RR + by) * RR;
#pragma unroll
    for (int z = 0; z < 8; z++) {
#pragma unroll
        for (int j = 0; j < 4; j++) {
            float v  = acc[j][z] + bv[j];
            float s  = v, s2 = v * v;
#pragma unroll
            for (int o = 8; o >= 1; o >>= 1) {
                s  += __shfl_xor_sync(0xffffffffu, s,  o, 16);
                s2 += __shfl_xor_sync(0xffffffffu, s2, o, 16);
            }
            float mu  = s * (1.0f / 16.0f);
            float var = s2 * (1.0f / 16.0f) - mu * mu;
            float rs  = rsqrtf(var + 1e-5f);
            float y   = (v - mu) * rs * gm[j] + bt[j];
            y = y / (1.0f + expf(-y));                    // SiLU
            outp[(vbase + z0 + z) * COUT + c0 + 32 * j] = y;
        }
    }
}

// ---------------- point branch: 1x1 conv (GEMM) + global group stats ----------
// block = 32 points x 128 channels; 128 threads (thread = channel).
__global__ void __launch_bounds__(128)
mlp_gstats_kernel(const float* __restrict__ feats,
                  const float* __restrict__ w,
                  const float* __restrict__ bias) {
    __shared__ float s_w[CIN0 * 129];        // [ci][c], pitch 129 (conflict-free)
    __shared__ float s_f[CIN0 * 32];         // [ci][p]
    const int tid = threadIdx.x;             // = channel c
    const int b   = blockIdx.x >> 9;         // 512 blocks per batch
    const int n0  = (blockIdx.x & 511) * 32;

    // load weights transposed: read coalesced w[c*64+ci], write s_w[ci*129+c]
    for (int i = tid; i < COUT * CIN0; i += 128) {
        int c = i >> 6, ci = i & 63;
        s_w[ci * 129 + c] = w[i];
    }
    // load features tile: [ci][p], coalesced along n
    for (int i = tid; i < CIN0 * 32; i += 128) {
        int ci = i >> 5, p = i & 31;
        s_f[ci * 32 + p] = feats[((size_t)b * CIN0 + ci) * NN + n0 + p];
    }
    __syncthreads();

    const int c = tid;
    float bv = bias[c];
    float lsum = 0.f, lsq = 0.f;
    for (int p = 0; p < 32; p++) {
        float a = bv;
#pragma unroll 16
        for (int ci = 0; ci < CIN0; ci++)
            a += s_w[ci * 129 + c] * s_f[ci * 32 + p];
        g_pf[((size_t)b * NN + n0 + p) * COUT + c] = a;
        lsum += a;
        lsq  += a * a;
    }
    // reduce over 16-lane group segments
#pragma unroll
    for (int o = 8; o >= 1; o >>= 1) {
        lsum += __shfl_xor_sync(0xffffffffu, lsum, o, 16);
        lsq  += __shfl_xor_sync(0xffffffffu, lsq,  o, 16);
    }
    if ((tid & 15) == 0) {
        int g = c >> 4;
        atomicAdd(&g_stats[(b * 8 + g) * 2 + 0], lsum);
        atomicAdd(&g_stats[(b * 8 + g) * 2 + 1], lsq);
    }
}

__global__ void stats_finalize_kernel() {
    int t = threadIdx.x;
    if (t >= BB * 8) return;
    const float inv = 1.0f / (16.0f * (float)NN);
    float s  = g_stats[t * 2 + 0];
    float s2 = g_stats[t * 2 + 1];
    float mu  = s * inv;
    float var = s2 * inv - mu * mu;
    g_stats[t * 2 + 0] = mu;
    g_stats[t * 2 + 1] = rsqrtf(var + 1e-5f);
}

// ---------------- devoxelize (trilinear) + point GN/SiLU + add ----------------
// block = 16 points x 128 channels; transpose through SMEM for coalesced [B,C,N] writes
__global__ void __launch_bounds__(128)
devox_out_kernel(const float* __restrict__ coords,
                 const float* __restrict__ gamma,
                 const float* __restrict__ beta,
                 float* __restrict__ out) {
    __shared__ float s_o[COUT * 17];          // [c][p], pitch 17
    const int c  = threadIdx.x;
    const int p0 = blockIdx.x * 16;           // global point base (same batch for 16 pts)
    const int b  = p0 >> 14;
    const int n0 = p0 & (NN - 1);
    const int g  = c >> 4;
    const float gm = gamma[c], bt = beta[c];
    const float mu = g_stats[(b * 8 + g) * 2 + 0];
    const float rs = g_stats[(b * 8 + g) * 2 + 1];

    for (int p = 0; p < 16; p++) {
        int gp = p0 + p;
        float cx = coords[gp * 3 + 0] * (float)RR;
        float cy = coords[gp * 3 + 1] * (float)RR;
        float cz = coords[gp * 3 + 2] * (float)RR;
        float fxl = floorf(cx), fyl = floorf(cy), fzl = floorf(cz);
        int ix = min(max((int)fxl, 0), RR - 1);
        int iy = min(max((int)fyl, 0), RR - 1);
        int iz = min(max((int)fzl, 0), RR - 1);
        int hx = min(ix + 1, RR - 1), hy = min(iy + 1, RR - 1), hz = min(iz + 1, RR - 1);
        float fx = cx - fxl, fy = cy - fyl, fz = cz - fzl;

        float v = 0.f;
#pragma unroll
        for (int dx = 0; dx < 2; dx++) {
            float wx = dx ? fx : 1.f - fx;
            int X = dx ? hx : ix;
#pragma unroll
            for (int dy = 0; dy < 2; dy++) {
                float wy = dy ? fy : 1.f - fy;
                int Y = dy ? hy : iy;
#pragma unroll
                for (int dz = 0; dz < 2; dz++) {
                    float wz = dz ? fz : 1.f - fz;
                    int Z = dz ? hz : iz;
                    size_t base = (((size_t)(b * RR + X) * RR + Y) * RR + Z) * COUT + c;
                    v += (wx * wy * wz) * g_h2[base];
                }
            }
        }
        // point branch: GN (precomputed global stats) + SiLU
        float pv = g_pf[((size_t)gp) * COUT + c];
        float y  = (pv - mu) * rs * gm + bt;
        y = y / (1.0f + expf(-y));
        s_o[c * 17 + p] = v + y;
    }
    __syncthreads();
    // write out[b][c][n] coalesced-ish (16 consecutive n per 16-lane segment)
    for (int i = threadIdx.x; i < COUT * 16; i += 128) {
        int c2 = i >> 4, p = i & 15;
        out[((size_t)b * COUT + c2) * NN + n0 + p] = s_o[c2 * 17 + p];
    }
}

// ---------------- launch ------------------------------------------------------
extern "C" void kernel_launch(void* const* d_in, const int* in_sizes, int n_in,
                              void* d_out, int out_size) {
    const float* coords   = (const float*)d_in[0];
    const float* features = (const float*)d_in[1];
    const float* conv1_w  = (const float*)d_in[2];
    const float* conv1_b  = (const float*)d_in[3];
    const float* gn1_g    = (const float*)d_in[4];
    const float* gn1_b    = (const float*)d_in[5];
    const float* conv2_w  = (const float*)d_in[6];
    const float* conv2_b  = (const float*)d_in[7];
    const float* gn2_g    = (const float*)d_in[8];
    const float* gn2_b    = (const float*)d_in[9];
    const float* mlp_w    = (const float*)d_in[10];
    const float* mlp_b    = (const float*)d_in[11];
    const float* gnp_g    = (const float*)d_in[12];
    const float* gnp_b    = (const float*)d_in[13];
    float* out = (float*)d_out;

    // 1) zero scratch (grid sums, counts, stats)
    zero_scratch_kernel<<<2048, 256>>>();

    // 2) transpose weights to [ci][tap][cout]
    wt_transpose_kernel<CIN0><<<(CIN0 * 27 * COUT + 255) / 256, 256>>>(conv1_w);
    wt_transpose_kernel<COUT><<<(COUT * 27 * COUT + 255) / 256, 256>>>(conv2_w);

    // 3) voxelize: scatter-add then average
    scatter_kernel<<<(BB * NN * CIN0 + 255) / 256, 256>>>(coords, features);
    vox_norm_kernel<<<4096, 256>>>();

    // 4) conv1 + GN + SiLU ; conv2 + GN + SiLU
    dim3 cgrid(RR, RR, BB);
    conv_gn_silu_kernel<CIN0><<<cgrid, 128>>>(conv1_b, gn1_g, gn1_b);
    conv_gn_silu_kernel<COUT><<<cgrid, 128>>>(conv2_b, gn2_g, gn2_b);

    // 5) point branch GEMM + group stats; finalize stats
    mlp_gstats_kernel<<<BB * (NN / 32), 128>>>(features, mlp_w, mlp_b);
    stats_finalize_kernel<<<1, 32>>>();

    // 6) devoxelize + point GN/SiLU + add -> out
    devox_out_kernel<<<BB * NN / 16, 128>>>(coords, gnp_g, gnp_b, out);
}

// round 2
// speedup vs baseline: 1.0602x; 1.0602x over previous
#include <cuda_runtime.h>
#include <math.h>

#define BB   4
#define NN   16384
#define CIN0 64
#define COUT 128
#define RR   32
#define NVOX (BB*RR*RR*RR)   /* 131072 */

typedef unsigned long long ull;

// ---------------- scratch (device globals; no allocation in kernel_launch) ----
__device__ float g_grid[(size_t)NVOX * CIN0];        // [b][x][y][z][64]   33.5 MB
__device__ float g_cnt [NVOX];                       //                     0.5 MB
__device__ float g_h1  [(size_t)NVOX * COUT];        // [b][x][y][z][128]  67 MB
__device__ float g_h2  [(size_t)NVOX * COUT];        //                    67 MB
__device__ float g_pf  [(size_t)BB * NN * COUT];     // [b][n][c]          33.5 MB
__device__ float g_stats[BB * 8 * 2];                // per (b,group): sum,sumsq -> mu,rs
__device__ float g_wt1 [CIN0 * 27 * COUT];           // [ci][tap][pair-interleaved co]
__device__ float g_wt2 [COUT * 27 * COUT];

// ---------------- f32x2 packed helpers ----------------------------------------
__device__ __forceinline__ ull dup2(float x) {
    ull r;
    asm("mov.b64 %0, {%1, %1};" : "=l"(r) : "f"(x));
    return r;
}
__device__ __forceinline__ void ffma2(ull& d, ull a, ull b, ull c) {
    asm("fma.rn.f32x2 %0, %1, %2, %3;" : "=l"(d) : "l"(a), "l"(b), "l"(c));
}
__device__ __forceinline__ void unpack2(float& lo, float& hi, ull v) {
    asm("mov.b64 {%0, %1}, %2;" : "=f"(lo), "=f"(hi) : "l"(v));
}

// ---------------- zero scratch ------------------------------------------------
__global__ void zero_scratch_kernel() {
    const long NG = (long)NVOX * CIN0;
    const long NC = NVOX;
    const long NS = BB * 8 * 2;
    const long total = NG + NC + NS;
    for (long i = (long)blockIdx.x * blockDim.x + threadIdx.x; i < total;
         i += (long)gridDim.x * blockDim.x) {
        if (i < NG)            g_grid[i] = 0.f;
        else if (i < NG + NC)  g_cnt[i - NG] = 0.f;
        else                   g_stats[i - NG - NC] = 0.f;
    }
}

// ---- weight transpose: w[co][ci][tap] -> wt[ci][tap][pair-interleaved co] ----
// pair layout within 128: pos = (co>=64 ? 64 : 0) + (co&31)*2 + ((co>>5)&1)
// so (c0, c0+32) and (c0+64, c0+96) are adjacent 8-byte-aligned pairs.
template <int CIN>
__global__ void wt_transpose_kernel(const float* __restrict__ w) {
    float* dst = (CIN == CIN0) ? g_wt1 : g_wt2;
    int total = CIN * 27 * COUT;
    for (int i = blockIdx.x * blockDim.x + threadIdx.x; i < total;
         i += gridDim.x * blockDim.x) {
        int co  = i / (CIN * 27);
        int r   = i - co * (CIN * 27);
        int ci  = r / 27;
        int tap = r - ci * 27;
        int pos = ((co >= 64) ? 64 : 0) + (co & 31) * 2 + ((co >> 5) & 1);
        dst[(ci * 27 + tap) * COUT + pos] = w[i];
    }
}

// ---------------- voxelize: scatter-add ---------------------------------------
__global__ void scatter_kernel(const float* __restrict__ coords,
                               const float* __restrict__ feats) {
    int idx = blockIdx.x * blockDim.x + threadIdx.x;     // over 65536*64
    if (idx >= BB * NN * CIN0) return;
    int ci = idx & (CIN0 - 1);
    int gp = idx >> 6;                                   // global point
    int b  = gp >> 14;
    int n  = gp & (NN - 1);
    float cx = coords[gp * 3 + 0] * (float)RR;
    float cy = coords[gp * 3 + 1] * (float)RR;
    float cz = coords[gp * 3 + 2] * (float)RR;
    int ix = min(max((int)floorf(cx), 0), RR - 1);
    int iy = min(max((int)floorf(cy), 0), RR - 1);
    int iz = min(max((int)floorf(cz), 0), RR - 1);
    int vox = ((b * RR + ix) * RR + iy) * RR + iz;
    atomicAdd(&g_grid[(size_t)vox * CIN0 + ci],
              feats[((size_t)b * CIN0 + ci) * NN + n]);
    if (ci == 0) atomicAdd(&g_cnt[vox], 1.0f);
}

__global__ void vox_norm_kernel() {
    long total = (long)NVOX * CIN0;
    for (long i = (long)blockIdx.x * blockDim.x + threadIdx.x; i < total;
         i += (long)gridDim.x * blockDim.x) {
        long v = i >> 6;
        float c = g_cnt[v];
        g_grid[i] *= 1.0f / fmaxf(c, 1.0f);
    }
}

// ---------------- fused conv3x3x3 + bias + per-voxel GN(16) + SiLU ------------
// block = (x, y, b) pencil over z. 128 threads: lane c0 = tid&31 (cout base),
// zq = tid>>5 (z quarter). Each thread: 4 couts (pairs via f32x2) x 8 z.
template <int CIN>
__global__ void __launch_bounds__(128)
conv_gn_silu_kernel(const float* __restrict__ bias,
                    const float* __restrict__ gamma,
                    const float* __restrict__ beta) {
    const float* in = (CIN == CIN0) ? g_grid : g_h1;
    const float* wt = (CIN == CIN0) ? g_wt1 : g_wt2;
    float* outp     = (CIN == CIN0) ? g_h1  : g_h2;

    constexpr int CHUNK = 16;
    constexpr int ZP = 35;                               // pitch (34 used) -> no STS conflicts
    __shared__ ull s2[9 * CHUNK * ZP];                   // [q][ci][zp], values duplicated (x,x)

    const int tid = threadIdx.x;
    const int c0  = tid & 31;
    const int zq  = tid >> 5;
    const int z0  = zq * 8;
    const int bx = blockIdx.x, by = blockIdx.y, bb = blockIdx.z;

    ull acc01[8], acc23[8];
#pragma unroll
    for (int z = 0; z < 8; z++) { acc01[z] = 0ull; acc23[z] = 0ull; }

    for (int cb = 0; cb < CIN; cb += CHUNK) {
        __syncthreads();
        // load halo: 9 columns x 34 zp x 16 ci (float4 from gmem, duplicated into smem)
        for (int i = tid; i < 9 * 34 * (CHUNK / 4); i += 128) {
            int ci4 = i & 3;
            int zp  = (i >> 2) % 34;
            int q   = i / (4 * 34);
            int dx = q / 3, dy = q % 3;
            int gx = bx + dx - 1, gy = by + dy - 1, gz = zp - 1;
            float4 v = make_float4(0.f, 0.f, 0.f, 0.f);
            if ((unsigned)gx < RR && (unsigned)gy < RR && (unsigned)gz < RR) {
                v = *(const float4*)&in[((((size_t)bb * RR + gx) * RR + gy) * RR + gz) * CIN
                                        + cb + ci4 * 4];
            }
            int base = (q * CHUNK + ci4 * 4) * ZP + zp;
            s2[base]          = dup2(v.x);
            s2[base + ZP]     = dup2(v.y);
            s2[base + 2 * ZP] = dup2(v.z);
            s2[base + 3 * ZP] = dup2(v.w);
        }
        __syncthreads();

#pragma unroll 1
        for (int ci = 0; ci < CHUNK; ci++) {
#pragma unroll 1
            for (int q = 0; q < 9; q++) {
                // register-cache the 10 z-positions this thread needs (broadcast LDS.64)
                ull xv[10];
                const ull* sp = &s2[(q * CHUNK + ci) * ZP + z0];
#pragma unroll
                for (int m = 0; m < 10; m++) xv[m] = sp[m];
                const float* wp = &wt[((size_t)(cb + ci) * 27 + q * 3) * COUT];
#pragma unroll
                for (int dz = 0; dz < 3; dz++) {
                    ull w01 = *(const ull*)&wp[dz * COUT + c0 * 2];
                    ull w23 = *(const ull*)&wp[dz * COUT + 64 + c0 * 2];
#pragma unroll
                    for (int z = 0; z < 8; z++) {
                        ffma2(acc01[z], w01, xv[dz + z], acc01[z]);
                        ffma2(acc23[z], w23, xv[dz + z], acc23[z]);
                    }
                }
            }
        }
    }

    // epilogue: bias + GroupNorm over 16 channels (16-lane segments) + SiLU
    float bv[4], gm[4], bt[4];
#pragma unroll
    for (int j = 0; j < 4; j++) {
        int c = c0 + 32 * j;
        bv[j] = bias[c]; gm[j] = gamma[c]; bt[j] = beta[c];
    }
    size_t vbase = (((size_t)bb * RR + bx) * RR + by) * RR;
#pragma unroll
    for (int z = 0; z < 8; z++) {
        float a[4];
        unpack2(a[0], a[1], acc01[z]);
        unpack2(a[2], a[3], acc23[z]);
#pragma unroll
        for (int j = 0; j < 4; j++) {
            float v  = a[j] + bv[j];
            float s  = v, s2r = v * v;
#pragma unroll
            for (int o = 8; o >= 1; o >>= 1) {
                s   += __shfl_xor_sync(0xffffffffu, s,   o, 16);
                s2r += __shfl_xor_sync(0xffffffffu, s2r, o, 16);
            }
            float mu  = s * (1.0f / 16.0f);
            float var = s2r * (1.0f / 16.0f) - mu * mu;
            float rs  = rsqrtf(var + 1e-5f);
            float y   = (v - mu) * rs * gm[j] + bt[j];
            y = y / (1.0f + expf(-y));                    // SiLU
            outp[(vbase + z0 + z) * COUT + c0 + 32 * j] = y;
        }
    }
}

// ---------------- point branch: 1x1 conv (GEMM) + global group stats ----------
// block = 32 points x 128 channels; 128 threads (thread = channel).
__global__ void __launch_bounds__(128)
mlp_gstats_kernel(const float* __restrict__ feats,
                  const float* __restrict__ w,
                  const float* __restrict__ bias) {
    __shared__ float s_w[CIN0 * 129];        // [ci][c], pitch 129 (conflict-free)
    __shared__ float s_f[CIN0 * 32];         // [ci][p]
    const int tid = threadIdx.x;             // = channel c
    const int b   = blockIdx.x >> 9;         // 512 blocks per batch
    const int n0  = (blockIdx.x & 511) * 32;

    for (int i = tid; i < COUT * CIN0; i += 128) {
        int c = i >> 6, ci = i & 63;
        s_w[ci * 129 + c] = w[i];
    }
    for (int i = tid; i < CIN0 * 32; i += 128) {
        int ci = i >> 5, p = i & 31;
        s_f[ci * 32 + p] = feats[((size_t)b * CIN0 + ci) * NN + n0 + p];
    }
    __syncthreads();

    const int c = tid;
    float bv = bias[c];
    float lsum = 0.f, lsq = 0.f;
    for (int p = 0; p < 32; p++) {
        float a = bv;
#pragma unroll 16
        for (int ci = 0; ci < CIN0; ci++)
            a += s_w[ci * 129 + c] * s_f[ci * 32 + p];
        g_pf[((size_t)b * NN + n0 + p) * COUT + c] = a;
        lsum += a;
        lsq  += a * a;
    }
#pragma unroll
    for (int o = 8; o >= 1; o >>= 1) {
        lsum += __shfl_xor_sync(0xffffffffu, lsum, o, 16);
        lsq  += __shfl_xor_sync(0xffffffffu, lsq,  o, 16);
    }
    if ((tid & 15) == 0) {
        int g = c >> 4;
        atomicAdd(&g_stats[(b * 8 + g) * 2 + 0], lsum);
        atomicAdd(&g_stats[(b * 8 + g) * 2 + 1], lsq);
    }
}

__global__ void stats_finalize_kernel() {
    int t = threadIdx.x;
    if (t >= BB * 8) return;
    const float inv = 1.0f / (16.0f * (float)NN);
    float s  = g_stats[t * 2 + 0];
    float s2 = g_stats[t * 2 + 1];
    float mu  = s * inv;
    float var = s2 * inv - mu * mu;
    g_stats[t * 2 + 0] = mu;
    g_stats[t * 2 + 1] = rsqrtf(var + 1e-5f);
}

// ---------------- devoxelize (trilinear) + point GN/SiLU + add ----------------
__global__ void __launch_bounds__(128)
devox_out_kernel(const float* __restrict__ coords,
                 const float* __restrict__ gamma,
                 const float* __restrict__ beta,
                 float* __restrict__ out) {
    __shared__ float s_o[COUT * 17];          // [c][p], pitch 17
    const int c  = threadIdx.x;
    const int p0 = blockIdx.x * 16;           // global point base (same batch for 16 pts)
    const int b  = p0 >> 14;
    const int n0 = p0 & (NN - 1);
    const int g  = c >> 4;
    const float gm = gamma[c], bt = beta[c];
    const float mu = g_stats[(b * 8 + g) * 2 + 0];
    const float rs = g_stats[(b * 8 + g) * 2 + 1];

    for (int p = 0; p < 16; p++) {
        int gp = p0 + p;
        float cx = coords[gp * 3 + 0] * (float)RR;
        float cy = coords[gp * 3 + 1] * (float)RR;
        float cz = coords[gp * 3 + 2] * (float)RR;
        float fxl = floorf(cx), fyl = floorf(cy), fzl = floorf(cz);
        int ix = min(max((int)fxl, 0), RR - 1);
        int iy = min(max((int)fyl, 0), RR - 1);
        int iz = min(max((int)fzl, 0), RR - 1);
        int hx = min(ix + 1, RR - 1), hy = min(iy + 1, RR - 1), hz = min(iz + 1, RR - 1);
        float fx = cx - fxl, fy = cy - fyl, fz = cz - fzl;

        float v = 0.f;
#pragma unroll
        for (int dx = 0; dx < 2; dx++) {
            float wx = dx ? fx : 1.f - fx;
            int X = dx ? hx : ix;
#pragma unroll
            for (int dy = 0; dy < 2; dy++) {
                float wy = dy ? fy : 1.f - fy;
                int Y = dy ? hy : iy;
#pragma unroll
                for (int dz = 0; dz < 2; dz++) {
                    float wz = dz ? fz : 1.f - fz;
                    int Z = dz ? hz : iz;
                    size_t base = (((size_t)(b * RR + X) * RR + Y) * RR + Z) * COUT + c;
                    v += (wx * wy * wz) * g_h2[base];
                }
            }
        }
        float pv = g_pf[((size_t)gp) * COUT + c];
        float y  = (pv - mu) * rs * gm + bt;
        y = y / (1.0f + expf(-y));
        s_o[c * 17 + p] = v + y;
    }
    __syncthreads();
    for (int i = threadIdx.x; i < COUT * 16; i += 128) {
        int c2 = i >> 4, p = i & 15;
        out[((size_t)b * COUT + c2) * NN + n0 + p] = s_o[c2 * 17 + p];
    }
}

// ---------------- launch ------------------------------------------------------
extern "C" void kernel_launch(void* const* d_in, const int* in_sizes, int n_in,
                              void* d_out, int out_size) {
    const float* coords   = (const float*)d_in[0];
    const float* features = (const float*)d_in[1];
    const float* conv1_w  = (const float*)d_in[2];
    const float* conv1_b  = (const float*)d_in[3];
    const float* gn1_g    = (const float*)d_in[4];
    const float* gn1_b    = (const float*)d_in[5];
    const float* conv2_w  = (const float*)d_in[6];
    const float* conv2_b  = (const float*)d_in[7];
    const float* gn2_g    = (const float*)d_in[8];
    const float* gn2_b    = (const float*)d_in[9];
    const float* mlp_w    = (const float*)d_in[10];
    const float* mlp_b    = (const float*)d_in[11];
    const float* gnp_g    = (const float*)d_in[12];
    const float* gnp_b    = (const float*)d_in[13];
    float* out = (float*)d_out;

    zero_scratch_kernel<<<2048, 256>>>();

    wt_transpose_kernel<CIN0><<<(CIN0 * 27 * COUT + 255) / 256, 256>>>(conv1_w);
    wt_transpose_kernel<COUT><<<(COUT * 27 * COUT + 255) / 256, 256>>>(conv2_w);

    scatter_kernel<<<(BB * NN * CIN0 + 255) / 256, 256>>>(coords, features);
    vox_norm_kernel<<<4096, 256>>>();

    dim3 cgrid(RR, RR, BB);
    conv_gn_silu_kernel<CIN0><<<cgrid, 128>>>(conv1_b, gn1_g, gn1_b);
    conv_gn_silu_kernel<COUT><<<cgrid, 128>>>(conv2_b, gn2_g, gn2_b);

    mlp_gstats_kernel<<<BB * (NN / 32), 128>>>(features, mlp_w, mlp_b);
    stats_finalize_kernel<<<1, 32>>>();

    devox_out_kernel<<<BB * NN / 16, 128>>>(coords, gnp_g, gnp_b, out);
}

// round 4
// speedup vs baseline: 2.4475x; 2.3086x over previous
#include <cuda_runtime.h>
#include <cuda_bf16.h>
#include <math.h>
#include <stdint.h>

#define BB   4
#define NN   16384
#define CIN0 64
#define COUT 128
#define RR   32
#define NVOX (BB*RR*RR*RR)   /* 131072 */

typedef unsigned int u32;
typedef unsigned long long u64;

// ---------------- scratch (device globals) ------------------------------------
__device__ float g_grid[(size_t)NVOX * CIN0];
__device__ float g_cnt [NVOX];
__device__ __align__(16) __nv_bfloat16 g_g0h[(size_t)NVOX * CIN0];
__device__ __align__(16) __nv_bfloat16 g_g0l[(size_t)NVOX * CIN0];
__device__ __align__(16) __nv_bfloat16 g_h1h[(size_t)NVOX * COUT];
__device__ __align__(16) __nv_bfloat16 g_h1l[(size_t)NVOX * COUT];
__device__ float g_h2  [(size_t)NVOX * COUT];
__device__ float g_pf  [(size_t)BB * NN * COUT];
__device__ float g_stats[BB * 8 * 2];
__device__ __align__(16) __nv_bfloat16 g_w1h[27 * COUT * CIN0];   // [tap][co][ci]
__device__ __align__(16) __nv_bfloat16 g_w1l[27 * COUT * CIN0];
__device__ __align__(16) __nv_bfloat16 g_w2h[27 * COUT * COUT];
__device__ __align__(16) __nv_bfloat16 g_w2l[27 * COUT * COUT];

// ---------------- helpers -------------------------------------------------------
__device__ __forceinline__ u32 smem_u32(const void* p) {
    u32 a;
    asm("{ .reg .u64 t; cvta.to.shared.u64 t, %1; cvt.u32.u64 %0, t; }" : "=r"(a) : "l"(p));
    return a;
}
__device__ __forceinline__ void cp16(u32 dst, const void* src, u32 sz) {
    asm volatile("cp.async.cg.shared.global [%0], [%1], 16, %2;"
                 :: "r"(dst), "l"(src), "r"(sz) : "memory");
}
__device__ __forceinline__ void ldsm4(u32& r0, u32& r1, u32& r2, u32& r3, u32 a) {
    asm volatile("ldmatrix.sync.aligned.m8n8.x4.shared.b16 {%0,%1,%2,%3}, [%4];"
                 : "=r"(r0), "=r"(r1), "=r"(r2), "=r"(r3) : "r"(a));
}
__device__ __forceinline__ void mma16816(float& d0, float& d1, float& d2, float& d3,
                                         u32 a0, u32 a1, u32 a2, u32 a3,
                                         u32 b0, u32 b1) {
    asm volatile("mma.sync.aligned.m16n8k16.row.col.f32.bf16.bf16.f32 "
                 "{%0,%1,%2,%3}, {%4,%5,%6,%7}, {%8,%9}, {%0,%1,%2,%3};"
                 : "+f"(d0), "+f"(d1), "+f"(d2), "+f"(d3)
                 : "r"(a0), "r"(a1), "r"(a2), "r"(a3), "r"(b0), "r"(b1));
}

// ---------------- zero scratch --------------------------------------------------
__global__ void zero_scratch_kernel() {
    const long NG = (long)NVOX * CIN0, NC = NVOX, NS = BB * 8 * 2;
    const long total = NG + NC + NS;
    for (long i = (long)blockIdx.x * blockDim.x + threadIdx.x; i < total;
         i += (long)gridDim.x * blockDim.x) {
        if (i < NG)            g_grid[i] = 0.f;
        else if (i < NG + NC)  g_cnt[i - NG] = 0.f;
        else                   g_stats[i - NG - NC] = 0.f;
    }
}

// ---- weight prep: w[co][ci][tap] -> [tap][co][ci] bf16 hi/lo --------------------
template <int CIN>
__global__ void wprep_kernel(const float* __restrict__ w) {
    __nv_bfloat16* oh = (CIN == CIN0) ? g_w1h : g_w2h;
    __nv_bfloat16* ol = (CIN == CIN0) ? g_w1l : g_w2l;
    int total = COUT * CIN * 27;
    for (int i = blockIdx.x * blockDim.x + threadIdx.x; i < total;
         i += gridDim.x * blockDim.x) {
        int co  = i / (CIN * 27);
        int r   = i - co * (CIN * 27);
        int ci  = r / 27;
        int tap = r - ci * 27;
        float v = w[i];
        __nv_bfloat16 h = __float2bfloat16(v);
        __nv_bfloat16 l = __float2bfloat16(v - __bfloat162float(h));
        int dst = (tap * COUT + co) * CIN + ci;
        oh[dst] = h; ol[dst] = l;
    }
}

// ---------------- voxelize -------------------------------------------------------
__global__ void scatter_kernel(const float* __restrict__ coords,
                               const float* __restrict__ feats) {
    int idx = blockIdx.x * blockDim.x + threadIdx.x;
    if (idx >= BB * NN * CIN0) return;
    int ci = idx & (CIN0 - 1);
    int gp = idx >> 6;
    int b  = gp >> 14;
    int n  = gp & (NN - 1);
    float cx = coords[gp * 3 + 0] * (float)RR;
    float cy = coords[gp * 3 + 1] * (float)RR;
    float cz = coords[gp * 3 + 2] * (float)RR;
    int ix = min(max((int)floorf(cx), 0), RR - 1);
    int iy = min(max((int)floorf(cy), 0), RR - 1);
    int iz = min(max((int)floorf(cz), 0), RR - 1);
    int vox = ((b * RR + ix) * RR + iy) * RR + iz;
    atomicAdd(&g_grid[(size_t)vox * CIN0 + ci],
              feats[((size_t)b * CIN0 + ci) * NN + n]);
    if (ci == 0) atomicAdd(&g_cnt[vox], 1.0f);
}

__global__ void vox_split_kernel() {
    long total = (long)NVOX * CIN0;
    for (long i = (long)blockIdx.x * blockDim.x + threadIdx.x; i < total;
         i += (long)gridDim.x * blockDim.x) {
        long v = i >> 6;
        float c = g_cnt[v];
        float val = g_grid[i] * (1.0f / fmaxf(c, 1.0f));
        __nv_bfloat16 h = __float2bfloat16(val);
        g_g0h[i] = h;
        g_g0l[i] = __float2bfloat16(val - __bfloat162float(h));
    }
}

// ---------------- mma.sync conv: implicit GEMM + GN + SiLU ----------------------
// CTA: (b,x) slab, 4 y-rows x 32 z = M128 voxel rows; N=128 couts.
// Buffers: {Ah, Al, Wh, Wl} each 128 rows x 128B @ pitch 144B, double-buffered.
#define PITCH   144
#define TEN_SZ  (128 * PITCH)        /* 18432 */
#define BUF_SZ  (4 * TEN_SZ)         /* 73728 */
#define CVSMEM  (2 * BUF_SZ)         /* 147456 */

template <int CIN>
__device__ __forceinline__ void load_chunk(
    int c, int buf, u32 sb, int tid, int b, int x, int y0,
    const __nv_bfloat16* inh, const __nv_bfloat16* inl,
    const __nv_bfloat16* wph, const __nv_bfloat16* wpl) {
    const int tap = (CIN == 128) ? (c >> 1) : c;
    const int ci0 = (CIN == 128) ? ((c & 1) * 64) : 0;
    const int dx = tap / 9, dy = (tap / 3) % 3, dz = tap % 3;
    const int gx = x + dx - 1;
    const u32 base = sb + buf * BUF_SZ;
#pragma unroll
    for (int i = 0; i < 16; i++) {
        int unit = tid + i * 256;
        int tensor = unit >> 10;
        int rest = unit & 1023;
        int row = rest >> 3, c16 = rest & 7;
        u32 dst = base + tensor * TEN_SZ + row * PITCH + c16 * 16;
        if (tensor < 2) {
            int gy = y0 + (row >> 5) + dy - 1;
            int gz = (row & 31) + dz - 1;
            bool ok = ((unsigned)gx < 32u) & ((unsigned)gy < 32u) & ((unsigned)gz < 32u);
            size_t off = 0;
            if (ok)
                off = ((((size_t)(b * 32 + gx)) * 32 + gy) * 32 + gz) * CIN + ci0 + c16 * 8;
            const __nv_bfloat16* src = (tensor ? inl : inh) + off;
            cp16(dst, src, ok ? 16u : 0u);
        } else {
            size_t off = ((size_t)tap * COUT + row) * CIN + ci0 + c16 * 8;
            const __nv_bfloat16* src = ((tensor == 2) ? wph : wpl) + off;
            cp16(dst, src, 16u);
        }
    }
    asm volatile("cp.async.commit_group;" ::: "memory");
}

template <int CIN>
__global__ void __launch_bounds__(256)
conv_mma_kernel(const float* __restrict__ bias,
                const float* __restrict__ gamma,
                const float* __restrict__ beta) {
    extern __shared__ __align__(128) char smem[];
    constexpr int L = (CIN == 128) ? 54 : 27;
    const u32 sb = smem_u32(smem);
    const int tid = threadIdx.x, w = tid >> 5, lane = tid & 31;
    const int x = blockIdx.x, y0 = blockIdx.y * 4, b = blockIdx.z;

    const __nv_bfloat16* inh = (CIN == 64) ? g_g0h : g_h1h;
    const __nv_bfloat16* inl = (CIN == 64) ? g_g0l : g_h1l;
    const __nv_bfloat16* wph = (CIN == 64) ? g_w1h : g_w2h;
    const __nv_bfloat16* wpl = (CIN == 64) ? g_w1l : g_w2l;

    float acc[16][4];
#pragma unroll
    for (int n = 0; n < 16; n++)
#pragma unroll
        for (int j = 0; j < 4; j++) acc[n][j] = 0.f;

    load_chunk<CIN>(0, 0, sb, tid, b, x, y0, inh, inl, wph, wpl);

#pragma unroll 1
    for (int c = 0; c < L; c++) {
        asm volatile("cp.async.wait_group 0;" ::: "memory");
        __syncthreads();
        if (c + 1 < L)
            load_chunk<CIN>(c + 1, (c + 1) & 1, sb, tid, b, x, y0, inh, inl, wph, wpl);

        const u32 abase = sb + (c & 1) * BUF_SZ;
        // per-warp A base: rows w*16 + (lane&15); 16B half select by lane>>4
        const u32 a_addr0 = abase + (w * 16 + (lane & 15)) * PITCH + (lane >> 4) * 16;
        const u32 b_row = (lane & 7) + ((lane >> 3) & 1) * 8;
        const u32 b_addr0 = abase + 2 * TEN_SZ + b_row * PITCH + (lane >> 4) * 16;
#pragma unroll
        for (int ks = 0; ks < 4; ks++) {
            u32 ah0, ah1, ah2, ah3, al0, al1, al2, al3;
            ldsm4(ah0, ah1, ah2, ah3, a_addr0 + ks * 32);
            ldsm4(al0, al1, al2, al3, a_addr0 + TEN_SZ + ks * 32);
#pragma unroll
            for (int ng = 0; ng < 8; ng++) {
                u32 wh0, wh1, wh2, wh3, wl0, wl1, wl2, wl3;
                u32 ba = b_addr0 + ng * 16 * PITCH + ks * 32;
                ldsm4(wh0, wh1, wh2, wh3, ba);
                ldsm4(wl0, wl1, wl2, wl3, ba + TEN_SZ);
                float* d0 = acc[2 * ng];
                float* d1 = acc[2 * ng + 1];
                mma16816(d0[0], d0[1], d0[2], d0[3], ah0, ah1, ah2, ah3, wh0, wh2);
                mma16816(d0[0], d0[1], d0[2], d0[3], al0, al1, al2, al3, wh0, wh2);
                mma16816(d0[0], d0[1], d0[2], d0[3], ah0, ah1, ah2, ah3, wl0, wl2);
                mma16816(d1[0], d1[1], d1[2], d1[3], ah0, ah1, ah2, ah3, wh1, wh3);
                mma16816(d1[0], d1[1], d1[2], d1[3], al0, al1, al2, al3, wh1, wh3);
                mma16816(d1[0], d1[1], d1[2], d1[3], ah0, ah1, ah2, ah3, wl1, wl3);
            }
        }
        __syncthreads();
    }

    // ---- epilogue: bias + per-voxel GN(16 ch) + SiLU, straight from fragments ----
    const int r0 = lane >> 2, cq = lane & 3;
#pragma unroll
    for (int h = 0; h < 2; h++) {
        int row_m = w * 16 + r0 + h * 8;
        int yl = row_m >> 5, z = row_m & 31;
        size_t vox = (((size_t)(b * 32 + x)) * 32 + (y0 + yl)) * 32 + z;
#pragma unroll
        for (int g = 0; g < 8; g++) {
            float v[4];
            int cA = g * 16 + cq * 2;       // cols of ntile 2g
            int cB = g * 16 + 8 + cq * 2;   // cols of ntile 2g+1
            v[0] = acc[2 * g][2 * h + 0]     + bias[cA + 0];
            v[1] = acc[2 * g][2 * h + 1]     + bias[cA + 1];
            v[2] = acc[2 * g + 1][2 * h + 0] + bias[cB + 0];
            v[3] = acc[2 * g + 1][2 * h + 1] + bias[cB + 1];
            float s = v[0] + v[1] + v[2] + v[3];
            float q = v[0] * v[0] + v[1] * v[1] + v[2] * v[2] + v[3] * v[3];
            s += __shfl_xor_sync(0xffffffffu, s, 1);
            s += __shfl_xor_sync(0xffffffffu, s, 2);
            q += __shfl_xor_sync(0xffffffffu, q, 1);
            q += __shfl_xor_sync(0xffffffffu, q, 2);
            float mu  = s * (1.0f / 16.0f);
            float var = q * (1.0f / 16.0f) - mu * mu;
            float rs  = rsqrtf(var + 1e-5f);
            float y2[4];
#pragma unroll
            for (int j = 0; j < 4; j++) {
                int col = (j < 2) ? (cA + j) : (cB + (j - 2));
                float y = (v[j] - mu) * rs * gamma[col] + beta[col];
                y2[j] = y / (1.0f + expf(-y));
            }
            if (CIN == 64) {
                __nv_bfloat16 h0 = __float2bfloat16(y2[0]);
                __nv_bfloat16 h1 = __float2bfloat16(y2[1]);
                __nv_bfloat16 h2 = __float2bfloat16(y2[2]);
                __nv_bfloat16 h3 = __float2bfloat16(y2[3]);
                __nv_bfloat162 lA; lA.x = __float2bfloat16(y2[0] - __bfloat162float(h0));
                lA.y = __float2bfloat16(y2[1] - __bfloat162float(h1));
                __nv_bfloat162 lB; lB.x = __float2bfloat16(y2[2] - __bfloat162float(h2));
                lB.y = __float2bfloat16(y2[3] - __bfloat162float(h3));
                __nv_bfloat162 hA; hA.x = h0; hA.y = h1;
                __nv_bfloat162 hB; hB.x = h2; hB.y = h3;
                *(__nv_bfloat162*)&g_h1h[vox * COUT + cA] = hA;
                *(__nv_bfloat162*)&g_h1l[vox * COUT + cA] = lA;
                *(__nv_bfloat162*)&g_h1h[vox * COUT + cB] = hB;
                *(__nv_bfloat162*)&g_h1l[vox * COUT + cB] = lB;
            } else {
                *(float2*)&g_h2[vox * COUT + cA] = make_float2(y2[0], y2[1]);
                *(float2*)&g_h2[vox * COUT + cB] = make_float2(y2[2], y2[3]);
            }
        }
    }
}

// ---------------- point branch GEMM + global group stats ------------------------
__global__ void __launch_bounds__(128)
mlp_gstats_kernel(const float* __restrict__ feats,
                  const float* __restrict__ w,
                  const float* __restrict__ bias) {
    __shared__ float s_w[CIN0 * 129];
    __shared__ float s_f[CIN0 * 32];
    const int tid = threadIdx.x;
    const int b   = blockIdx.x >> 9;
    const int n0  = (blockIdx.x & 511) * 32;

    for (int i = tid; i < COUT * CIN0; i += 128) {
        int c = i >> 6, ci = i & 63;
        s_w[ci * 129 + c] = w[i];
    }
    for (int i = tid; i < CIN0 * 32; i += 128) {
        int ci = i >> 5, p = i & 31;
        s_f[ci * 32 + p] = feats[((size_t)b * CIN0 + ci) * NN + n0 + p];
    }
    __syncthreads();

    const int c = tid;
    float bv = bias[c];
    float lsum = 0.f, lsq = 0.f;
    for (int p = 0; p < 32; p++) {
        float a = bv;
#pragma unroll 16
        for (int ci = 0; ci < CIN0; ci++)
            a += s_w[ci * 129 + c] * s_f[ci * 32 + p];
        g_pf[((size_t)b * NN + n0 + p) * COUT + c] = a;
        lsum += a; lsq += a * a;
    }
#pragma unroll
    for (int o = 8; o >= 1; o >>= 1) {
        lsum += __shfl_xor_sync(0xffffffffu, lsum, o, 16);
        lsq  += __shfl_xor_sync(0xffffffffu, lsq,  o, 16);
    }
    if ((tid & 15) == 0) {
        int g = c >> 4;
        atomicAdd(&g_stats[(b * 8 + g) * 2 + 0], lsum);
        atomicAdd(&g_stats[(b * 8 + g) * 2 + 1], lsq);
    }
}

__global__ void stats_finalize_kernel() {
    int t = threadIdx.x;
    if (t >= BB * 8) return;
    const float inv = 1.0f / (16.0f * (float)NN);
    float s = g_stats[t * 2 + 0], s2 = g_stats[t * 2 + 1];
    float mu = s * inv;
    float var = s2 * inv - mu * mu;
    g_stats[t * 2 + 0] = mu;
    g_stats[t * 2 + 1] = rsqrtf(var + 1e-5f);
}

// ---------------- devoxelize + point GN/SiLU + add ------------------------------
__global__ void __launch_bounds__(128)
devox_out_kernel(const float* __restrict__ coords,
                 const float* __restrict__ gamma,
                 const float* __restrict__ beta,
                 float* __restrict__ out) {
    __shared__ float s_o[COUT * 17];
    const int c  = threadIdx.x;
    const int p0 = blockIdx.x * 16;
    const int b  = p0 >> 14;
    const int n0 = p0 & (NN - 1);
    const int g  = c >> 4;
    const float gm = gamma[c], bt = beta[c];
    const float mu = g_stats[(b * 8 + g) * 2 + 0];
    const float rs = g_stats[(b * 8 + g) * 2 + 1];

    for (int p = 0; p < 16; p++) {
        int gp = p0 + p;
        float cx = coords[gp * 3 + 0] * (float)RR;
        float cy = coords[gp * 3 + 1] * (float)RR;
        float cz = coords[gp * 3 + 2] * (float)RR;
        float fxl = floorf(cx), fyl = floorf(cy), fzl = floorf(cz);
        int ix = min(max((int)fxl, 0), RR - 1);
        int iy = min(max((int)fyl, 0), RR - 1);
        int iz = min(max((int)fzl, 0), RR - 1);
        int hx = min(ix + 1, RR - 1), hy = min(iy + 1, RR - 1), hz = min(iz + 1, RR - 1);
        float fx = cx - fxl, fy = cy - fyl, fz = cz - fzl;

        float v = 0.f;
#pragma unroll
        for (int dx = 0; dx < 2; dx++) {
            float wx = dx ? fx : 1.f - fx;
            int X = dx ? hx : ix;
#pragma unroll
            for (int dy = 0; dy < 2; dy++) {
                float wy = dy ? fy : 1.f - fy;
                int Y = dy ? hy : iy;
#pragma unroll
                for (int dz = 0; dz < 2; dz++) {
                    float wz = dz ? fz : 1.f - fz;
                    int Z = dz ? hz : iz;
                    size_t base = (((size_t)(b * RR + X) * RR + Y) * RR + Z) * COUT + c;
                    v += (wx * wy * wz) * g_h2[base];
                }
            }
        }
        float pv = g_pf[((size_t)gp) * COUT + c];
        float y  = (pv - mu) * rs * gm + bt;
        y = y / (1.0f + expf(-y));
        s_o[c * 17 + p] = v + y;
    }
    __syncthreads();
    for (int i = threadIdx.x; i < COUT * 16; i += 128) {
        int c2 = i >> 4, p = i & 15;
        out[((size_t)b * COUT + c2) * NN + n0 + p] = s_o[c2 * 17 + p];
    }
}

// ---------------- launch ----------------------------------------------------------
extern "C" void kernel_launch(void* const* d_in, const int* in_sizes, int n_in,
                              void* d_out, int out_size) {
    const float* coords   = (const float*)d_in[0];
    const float* features = (const float*)d_in[1];
    const float* conv1_w  = (const float*)d_in[2];
    const float* conv1_b  = (const float*)d_in[3];
    const float* gn1_g    = (const float*)d_in[4];
    const float* gn1_b    = (const float*)d_in[5];
    const float* conv2_w  = (const float*)d_in[6];
    const float* conv2_b  = (const float*)d_in[7];
    const float* gn2_g    = (const float*)d_in[8];
    const float* gn2_b    = (const float*)d_in[9];
    const float* mlp_w    = (const float*)d_in[10];
    const float* mlp_b    = (const float*)d_in[11];
    const float* gnp_g    = (const float*)d_in[12];
    const float* gnp_b    = (const float*)d_in[13];
    float* out = (float*)d_out;

    static int attr_done = 0;
    if (!attr_done) {
        cudaFuncSetAttribute(conv_mma_kernel<CIN0>,
                             cudaFuncAttributeMaxDynamicSharedMemorySize, CVSMEM);
        cudaFuncSetAttribute(conv_mma_kernel<COUT>,
                             cudaFuncAttributeMaxDynamicSharedMemorySize, CVSMEM);
        attr_done = 1;
    }

    zero_scratch_kernel<<<2048, 256>>>();
    wprep_kernel<CIN0><<<(COUT * CIN0 * 27 + 255) / 256, 256>>>(conv1_w);
    wprep_kernel<COUT><<<(COUT * COUT * 27 + 255) / 256, 256>>>(conv2_w);

    scatter_kernel<<<(BB * NN * CIN0 + 255) / 256, 256>>>(coords, features);
    vox_split_kernel<<<4096, 256>>>();

    dim3 cgrid(RR, 8, BB);   // x, y-tile, b
    conv_mma_kernel<CIN0><<<cgrid, 256, CVSMEM>>>(conv1_b, gn1_g, gn1_b);
    conv_mma_kernel<COUT><<<cgrid, 256, CVSMEM>>>(conv2_b, gn2_g, gn2_b);

    mlp_gstats_kernel<<<BB * (NN / 32), 128>>>(features, mlp_w, mlp_b);
    stats_finalize_kernel<<<1, 32>>>();

    devox_out_kernel<<<BB * NN / 16, 128>>>(coords, gnp_g, gnp_b, out);
}